// round 3
// baseline (speedup 1.0000x reference)
#include <cuda_runtime.h>

#define NPTS 65536
#define NCH 76          // 4*19
#define NF 64
#define NWORDS 2048     // 65536/32
#define CAP 2048        // max candidates per feature
#define NSAMP 2048

typedef unsigned long long u64;

__device__ unsigned g_masks[NCH * NWORDS];   // [ch][word]
__device__ int      g_popcnt[NCH];
__device__ float    g_zres[NCH * NF];
__device__ float    g_zf[NF];                // zero-point fallback feature
__device__ float    g_sfeat[NSAMP * NF];     // sample features [s][f]
__device__ float    g_T[NF];                 // per-feature candidate threshold
__device__ int      g_cnt[NF];
__device__ float    g_candv[NF * CAP];
__device__ int      g_candi[NF * CAP];

__device__ __forceinline__ float lrelu(float a) { return fmaxf(a, 0.01f * a); }

// ---- packed f32x2 helpers (sm_100+) ----
__device__ __forceinline__ u64 pk(float lo, float hi) {
    u64 r; asm("mov.b64 %0, {%1,%2};" : "=l"(r) : "f"(lo), "f"(hi)); return r;
}
__device__ __forceinline__ void unpk(u64 a, float& lo, float& hi) {
    asm("mov.b64 {%0,%1}, %2;" : "=f"(lo), "=f"(hi) : "l"(a));
}
__device__ __forceinline__ u64 ffma2(u64 a, u64 b, u64 c) {
    u64 d; asm("fma.rn.f32x2 %0, %1, %2, %3;" : "=l"(d) : "l"(a), "l"(b), "l"(c));
    return d;
}

// ---- shared-memory weight loader ----
__device__ __forceinline__ void load_mlp_smem(
    const float* w1, const float* b1, const float* w2, const float* b2,
    const float* w3, const float* b3,
    float* sw1, float* sb1, u64* sw2q, float* sb2, u64* sw3q, float* sb3,
    int tid, int nt)
{
    for (int i = tid; i < 128; i += nt) sw1[i] = w1[i];
    for (int i = tid; i < 64; i += nt) { sb1[i] = b1[i]; sb2[i] = b2[i]; sb3[i] = b3[i]; }
    for (int i = tid; i < 2048; i += nt) {
        sw2q[i] = ((const u64*)w2)[i];
        sw3q[i] = ((const u64*)w3)[i];
    }
}

// ---- full 3-layer MLP for one point (weights in smem) ----
__device__ __forceinline__ void mlp_point(
    float uu, float vv,
    const float* sw1, const float* sb1,
    const u64* sw2q, const float* sb2,
    const u64* sw3q, const float* sb3,
    float zs[64])
{
    u64 zq[32];
#pragma unroll
    for (int k = 0; k < 32; k++) {
        float a0 = fmaf(sw1[4 * k + 0], uu, fmaf(sw1[4 * k + 1], vv, sb1[2 * k]));
        float a1 = fmaf(sw1[4 * k + 2], uu, fmaf(sw1[4 * k + 3], vv, sb1[2 * k + 1]));
        zq[k] = pk(lrelu(a0), lrelu(a1));
    }
    float zt[64];
#pragma unroll
    for (int k = 0; k < 64; k++) {
        const ulonglong2* wr = (const ulonglong2*)(sw2q + k * 32);
        u64 a0 = 0ull, a1 = 0ull;
#pragma unroll
        for (int j2 = 0; j2 < 16; j2++) {
            ulonglong2 wv = wr[j2];
            a0 = ffma2(wv.x, zq[2 * j2 + 0], a0);
            a1 = ffma2(wv.y, zq[2 * j2 + 1], a1);
        }
        float l0, h0, l1, h1;
        unpk(a0, l0, h0); unpk(a1, l1, h1);
        zt[k] = lrelu((l0 + h0) + (l1 + h1) + sb2[k]);
    }
#pragma unroll
    for (int k = 0; k < 32; k++) zq[k] = pk(zt[2 * k], zt[2 * k + 1]);
#pragma unroll
    for (int k = 0; k < 64; k++) {
        const ulonglong2* wr = (const ulonglong2*)(sw3q + k * 32);
        u64 a0 = 0ull, a1 = 0ull;
#pragma unroll
        for (int j2 = 0; j2 < 16; j2++) {
            ulonglong2 wv = wr[j2];
            a0 = ffma2(wv.x, zq[2 * j2 + 0], a0);
            a1 = ffma2(wv.y, zq[2 * j2 + 1], a1);
        }
        float l0, h0, l1, h1;
        unpk(a0, l0, h0); unpk(a1, l1, h1);
        zs[k] = lrelu((l0 + h0) + (l1 + h1) + sb3[k]);
    }
}

#define SIDX(s) (((s) * 9973) & 65535)

// ---------------- prep: blocks 0..15 sample MLP; block 16 zeros + zero-feat ----------------
__global__ __launch_bounds__(128) void k_prep(
    const float* __restrict__ grid,
    const float* __restrict__ w1, const float* __restrict__ b1,
    const float* __restrict__ w2, const float* __restrict__ b2,
    const float* __restrict__ w3, const float* __restrict__ b3)
{
    int tid = threadIdx.x;
    if (blockIdx.x == 16) {
        __shared__ float z1[64], z2[64];
        if (tid < NCH) g_popcnt[tid] = 0;
        if (tid < NF) g_cnt[tid] = 0;
        if (tid < 64) z1[tid] = lrelu(b1[tid]);
        __syncthreads();
        if (tid < 64) {
            float a = b2[tid];
            for (int j = 0; j < 64; j++) a += w2[tid * 64 + j] * z1[j];
            z2[tid] = lrelu(a);
        }
        __syncthreads();
        if (tid < 64) {
            float a = b3[tid];
            for (int j = 0; j < 64; j++) a += w3[tid * 64 + j] * z2[j];
            g_zf[tid] = lrelu(a);
        }
        return;
    }
    __shared__ float sw1[128], sb1[64], sb2[64], sb3[64];
    __shared__ u64 sw2q[2048], sw3q[2048];
    load_mlp_smem(w1, b1, w2, b2, w3, b3, sw1, sb1, sw2q, sb2, sw3q, sb3, tid, 128);
    __syncthreads();

    int s = blockIdx.x * 128 + tid;
    int n = SIDX(s);
    float zs[64];
    mlp_point(grid[n], grid[NPTS + n], sw1, sb1, sw2q, sb2, sw3q, sb3, zs);
    float4* op = (float4*)(g_sfeat + s * 64);
#pragma unroll
    for (int k = 0; k < 16; k++)
        op[k] = make_float4(zs[4 * k], zs[4 * k + 1], zs[4 * k + 2], zs[4 * k + 3]);
}

// ---------------- pack masks + popcount; blocks 0,1 compute thresholds ----------------
__global__ __launch_bounds__(256) void k_pack(const int* __restrict__ x) {
    int tid = threadIdx.x;
    if (blockIdx.x < 2) {
        // threshold: per feature f, T = min over 32 lanes of (max over 64 samples)
        int wp = tid >> 5, lane = tid & 31;
        for (int q = 0; q < 4; q++) {
            int f = blockIdx.x * 32 + wp * 4 + q;
            float m = -1e30f;
            for (int i = 0; i < 64; i++)
                m = fmaxf(m, g_sfeat[(lane * 64 + i) * 64 + f]);
#pragma unroll
            for (int off = 16; off; off >>= 1)
                m = fminf(m, __shfl_xor_sync(0xffffffffu, m, off));
            if (lane == 0) g_T[f] = m;
        }
        return;
    }
    int g = (blockIdx.x - 2) * 256 + tid;   // g < NCH*NPTS
    int v = (x[g] == 1);
    unsigned ball = __ballot_sync(0xffffffffu, v);
    int lane = tid & 31;
    int wp = tid >> 5;
    __shared__ int s[8];
    if (lane == 0) {
        g_masks[g >> 5] = ball;
        s[wp] = __popc(ball);
    }
    __syncthreads();
    if (tid == 0) {
        int tot = 0;
#pragma unroll
        for (int i = 0; i < 8; i++) tot += s[i];
        atomicAdd(&g_popcnt[g >> 16], tot);
    }
}

// ---------------- full MLP + candidate collection (no feature store) ----------------
__global__ __launch_bounds__(128) void k_collect(
    const float* __restrict__ grid,
    const float* __restrict__ w1, const float* __restrict__ b1,
    const float* __restrict__ w2, const float* __restrict__ b2,
    const float* __restrict__ w3, const float* __restrict__ b3)
{
    __shared__ float sw1[128], sb1[64], sb2[64], sb3[64], sT[64];
    __shared__ u64 sw2q[2048], sw3q[2048];
    int tid = threadIdx.x;
    load_mlp_smem(w1, b1, w2, b2, w3, b3, sw1, sb1, sw2q, sb2, sw3q, sb3, tid, 128);
    if (tid < 64) sT[tid] = g_T[tid];
    __syncthreads();

    int n = blockIdx.x * 128 + tid;
    float zs[64];
    mlp_point(grid[n], grid[NPTS + n], sw1, sb1, sw2q, sb2, sw3q, sb3, zs);

#pragma unroll
    for (int k = 0; k < 64; k++) {
        if (zs[k] >= sT[k]) {
            int pos = atomicAdd(&g_cnt[k], 1);
            if (pos < CAP) {
                g_candv[k * CAP + pos] = zs[k];
                g_candi[k * CAP + pos] = n;
            }
        }
    }
}

// ---------------- per-feature masked max over candidates (+ exact fallback) ----------------
__global__ __launch_bounds__(128) void k_query(
    const float* __restrict__ grid,
    const float* __restrict__ w1, const float* __restrict__ b1,
    const float* __restrict__ w2, const float* __restrict__ b2,
    const float* __restrict__ w3, const float* __restrict__ b3)
{
    __shared__ int s_nfb;
    __shared__ unsigned char sflag[NCH];
    __shared__ float sw1[128], sb1[64], sb2[64], sb3[64];
    __shared__ u64 sw2q[2048], sw3q[2048];
    __shared__ float sred[128];

    int tid = threadIdx.x;
    int f = blockIdx.x;
    int cntRaw = g_cnt[f];
    int cnt = cntRaw < CAP ? cntRaw : CAP;
    bool overflow = cntRaw > CAP;

    if (tid == 0) s_nfb = 0;
    if (tid < NCH) sflag[tid] = 0;
    __syncthreads();

    if (tid < NCH) {
        int ch = tid;
        if (g_popcnt[ch] > 0) {
            float m = -1e30f;
            bool found = false;
            if (!overflow) {
                const unsigned* mw = g_masks + ch * NWORDS;
                const float* cv = g_candv + f * CAP;
                const int* ci = g_candi + f * CAP;
                for (int i = 0; i < cnt; i++) {
                    int n = __ldg(ci + i);
                    unsigned w = __ldg(mw + (n >> 5));
                    if ((w >> (n & 31)) & 1) { m = fmaxf(m, __ldg(cv + i)); found = true; }
                }
            }
            if (found) g_zres[ch * 64 + f] = m;
            else { sflag[ch] = 1; atomicAdd(&s_nfb, 1); }
        }
    }
    __syncthreads();
    if (s_nfb == 0) return;

    // exact dense fallback (astronomically rare): recompute MLP, masked max
    load_mlp_smem(w1, b1, w2, b2, w3, b3, sw1, sb1, sw2q, sb2, sw3q, sb3, tid, 128);
    __syncthreads();
    for (int ch = 0; ch < NCH; ch++) {
        if (!sflag[ch]) continue;
        const unsigned* mw = g_masks + ch * NWORDS;
        float m = -1e30f;
        for (int base = 0; base < NPTS; base += 128) {
            int n = base + tid;
            float zs[64];
            mlp_point(grid[n], grid[NPTS + n], sw1, sb1, sw2q, sb2, sw3q, sb3, zs);
            unsigned w = mw[n >> 5];
            if ((w >> (n & 31)) & 1) m = fmaxf(m, zs[f]);
        }
        sred[tid] = m;
        __syncthreads();
        for (int off = 64; off; off >>= 1) {
            if (tid < off) sred[tid] = fmaxf(sred[tid], sred[tid + off]);
            __syncthreads();
        }
        if (tid == 0) g_zres[ch * 64 + f] = sred[0];
        __syncthreads();
    }
}

// ---------------- final FC + repeat 18 ----------------
__global__ __launch_bounds__(128) void k_fc(const float* __restrict__ fcw,
                                            const float* __restrict__ fcb,
                                            float* __restrict__ out)
{
    __shared__ float fs[NCH * NF];
    __shared__ float rw[4][4];

    int tid = threadIdx.x;
    int o = blockIdx.x;
    for (int i = tid; i < NCH * NF; i += 128) {
        int ch = i >> 6;
        fs[i] = (g_popcnt[ch] > 0) ? g_zres[i] : g_zf[i & 63];
    }
    __syncthreads();

    float p0 = 0.f, p1 = 0.f, p2 = 0.f, p3 = 0.f;
    const float* wr = fcw + o * 1216;
    for (int k = tid; k < 1216; k += 128) {
        float w = wr[k];
        p0 += w * fs[k];
        p1 += w * fs[1216 + k];
        p2 += w * fs[2432 + k];
        p3 += w * fs[3648 + k];
    }
#pragma unroll
    for (int off = 16; off; off >>= 1) {
        p0 += __shfl_xor_sync(0xffffffffu, p0, off);
        p1 += __shfl_xor_sync(0xffffffffu, p1, off);
        p2 += __shfl_xor_sync(0xffffffffu, p2, off);
        p3 += __shfl_xor_sync(0xffffffffu, p3, off);
    }
    int lane = tid & 31, wp = tid >> 5;
    if (lane == 0) { rw[wp][0] = p0; rw[wp][1] = p1; rw[wp][2] = p2; rw[wp][3] = p3; }
    __syncthreads();
    if (tid < 4) {
        float s = rw[0][tid] + rw[1][tid] + rw[2][tid] + rw[3][tid];
        float scale = rsqrtf(1216.0f);
        float val = s * scale + fcb[o];
#pragma unroll
        for (int r = 0; r < 18; r++)
            out[(tid * 18 + r) * 512 + o] = val;
    }
}

extern "C" void kernel_launch(void* const* d_in, const int* in_sizes, int n_in,
                              void* d_out, int out_size) {
    const int*   x    = (const int*)d_in[0];
    const float* grid = (const float*)d_in[1];
    const float* w1   = (const float*)d_in[2];
    const float* b1   = (const float*)d_in[3];
    const float* w2   = (const float*)d_in[4];
    const float* b2   = (const float*)d_in[5];
    const float* w3   = (const float*)d_in[6];
    const float* b3   = (const float*)d_in[7];
    const float* fcw  = (const float*)d_in[8];
    const float* fcb  = (const float*)d_in[9];
    float* out = (float*)d_out;

    k_prep<<<17, 128>>>(grid, w1, b1, w2, b2, w3, b3);
    k_pack<<<2 + NCH * NPTS / 256, 256>>>(x);
    k_collect<<<NPTS / 128, 128>>>(grid, w1, b1, w2, b2, w3, b3);
    k_query<<<NF, 128>>>(grid, w1, b1, w2, b2, w3, b3);
    k_fc<<<512, 128>>>(fcw, fcb, out);
}

// round 4
// speedup vs baseline: 1.0331x; 1.0331x over previous
#include <cuda_runtime.h>

#define NPTS 65536
#define NCH 76          // 4*19
#define NF 64
#define CAP 4096        // max candidates per feature (expected ~130)
#define NSAMP 2048
#define NPACKBLK (NCH * NPTS / 128)   // 38912
#define NCOLBLK (NPTS / 128)          // 512

typedef unsigned long long u64;

__device__ unsigned g_maskT[2048 * NCH];     // [word_in_ch][ch] transposed
__device__ int      g_popcnt[NCH];
__device__ float    g_zres[NCH * NF];
__device__ float    g_zf[NF];                // zero-point fallback feature
__device__ float    g_sfeat[NSAMP * NF];     // sample features [s][f]
__device__ float    g_T[NF];                 // per-feature candidate threshold
__device__ int      g_cnt[NF];
__device__ int2     g_cand[NF * CAP];        // (.x = point idx, .y = float bits)

__device__ __forceinline__ float lrelu(float a) { return fmaxf(a, 0.01f * a); }

// ---- packed f32x2 helpers (sm_100+) ----
__device__ __forceinline__ u64 pk(float lo, float hi) {
    u64 r; asm("mov.b64 %0, {%1,%2};" : "=l"(r) : "f"(lo), "f"(hi)); return r;
}
__device__ __forceinline__ void unpk(u64 a, float& lo, float& hi) {
    asm("mov.b64 {%0,%1}, %2;" : "=f"(lo), "=f"(hi) : "l"(a));
}
__device__ __forceinline__ u64 ffma2(u64 a, u64 b, u64 c) {
    u64 d; asm("fma.rn.f32x2 %0, %1, %2, %3;" : "=l"(d) : "l"(a), "l"(b), "l"(c));
    return d;
}

// ---- shared-memory weight loader ----
__device__ __forceinline__ void load_mlp_smem(
    const float* w1, const float* b1, const float* w2, const float* b2,
    const float* w3, const float* b3,
    float* sw1, float* sb1, u64* sw2q, float* sb2, u64* sw3q, float* sb3,
    int tid, int nt)
{
    for (int i = tid; i < 128; i += nt) sw1[i] = w1[i];
    for (int i = tid; i < 64; i += nt) { sb1[i] = b1[i]; sb2[i] = b2[i]; sb3[i] = b3[i]; }
    for (int i = tid; i < 2048; i += nt) {
        sw2q[i] = ((const u64*)w2)[i];
        sw3q[i] = ((const u64*)w3)[i];
    }
}

// ---- full 3-layer MLP for one point (weights in smem) ----
__device__ __forceinline__ void mlp_point(
    float uu, float vv,
    const float* sw1, const float* sb1,
    const u64* sw2q, const float* sb2,
    const u64* sw3q, const float* sb3,
    float zs[64])
{
    u64 zq[32];
#pragma unroll
    for (int k = 0; k < 32; k++) {
        float a0 = fmaf(sw1[4 * k + 0], uu, fmaf(sw1[4 * k + 1], vv, sb1[2 * k]));
        float a1 = fmaf(sw1[4 * k + 2], uu, fmaf(sw1[4 * k + 3], vv, sb1[2 * k + 1]));
        zq[k] = pk(lrelu(a0), lrelu(a1));
    }
    float zt[64];
#pragma unroll
    for (int k = 0; k < 64; k++) {
        const ulonglong2* wr = (const ulonglong2*)(sw2q + k * 32);
        u64 a0 = 0ull, a1 = 0ull;
#pragma unroll
        for (int j2 = 0; j2 < 16; j2++) {
            ulonglong2 wv = wr[j2];
            a0 = ffma2(wv.x, zq[2 * j2 + 0], a0);
            a1 = ffma2(wv.y, zq[2 * j2 + 1], a1);
        }
        float l0, h0, l1, h1;
        unpk(a0, l0, h0); unpk(a1, l1, h1);
        zt[k] = lrelu((l0 + h0) + (l1 + h1) + sb2[k]);
    }
#pragma unroll
    for (int k = 0; k < 32; k++) zq[k] = pk(zt[2 * k], zt[2 * k + 1]);
#pragma unroll
    for (int k = 0; k < 64; k++) {
        const ulonglong2* wr = (const ulonglong2*)(sw3q + k * 32);
        u64 a0 = 0ull, a1 = 0ull;
#pragma unroll
        for (int j2 = 0; j2 < 16; j2++) {
            ulonglong2 wv = wr[j2];
            a0 = ffma2(wv.x, zq[2 * j2 + 0], a0);
            a1 = ffma2(wv.y, zq[2 * j2 + 1], a1);
        }
        float l0, h0, l1, h1;
        unpk(a0, l0, h0); unpk(a1, l1, h1);
        zs[k] = lrelu((l0 + h0) + (l1 + h1) + sb3[k]);
    }
}

#define SIDX(s) (((s) * 9973) & 65535)

// ---------------- prep: blocks 0..15 sample MLP; block 16 zeros + zero-feat ----------------
__global__ __launch_bounds__(128) void k_prep(
    const float* __restrict__ grid,
    const float* __restrict__ w1, const float* __restrict__ b1,
    const float* __restrict__ w2, const float* __restrict__ b2,
    const float* __restrict__ w3, const float* __restrict__ b3)
{
    int tid = threadIdx.x;
    if (blockIdx.x == 16) {
        __shared__ float z1[64], z2[64];
        if (tid < NCH) g_popcnt[tid] = 0;
        if (tid < NF) g_cnt[tid] = 0;
        if (tid < 64) z1[tid] = lrelu(b1[tid]);
        __syncthreads();
        if (tid < 64) {
            float a = b2[tid];
            for (int j = 0; j < 64; j++) a += w2[tid * 64 + j] * z1[j];
            z2[tid] = lrelu(a);
        }
        __syncthreads();
        if (tid < 64) {
            float a = b3[tid];
            for (int j = 0; j < 64; j++) a += w3[tid * 64 + j] * z2[j];
            g_zf[tid] = lrelu(a);
        }
        return;
    }
    __shared__ float sw1[128], sb1[64], sb2[64], sb3[64];
    __shared__ u64 sw2q[2048], sw3q[2048];
    load_mlp_smem(w1, b1, w2, b2, w3, b3, sw1, sb1, sw2q, sb2, sw3q, sb3, tid, 128);
    __syncthreads();

    int s = blockIdx.x * 128 + tid;
    int n = SIDX(s);
    float zs[64];
    mlp_point(grid[n], grid[NPTS + n], sw1, sb1, sw2q, sb2, sw3q, sb3, zs);
    float4* op = (float4*)(g_sfeat + s * 64);
#pragma unroll
    for (int k = 0; k < 16; k++)
        op[k] = make_float4(zs[4 * k], zs[4 * k + 1], zs[4 * k + 2], zs[4 * k + 3]);
}

// ---------------- select: per feature, T = 4th-smallest of 32 lane-maxes ----------------
__global__ __launch_bounds__(32) void k_select() {
    int f = blockIdx.x;
    int lane = threadIdx.x;
    float m = -3.402823466e38f;
    for (int i = 0; i < 64; i++)
        m = fmaxf(m, g_sfeat[(i * 32 + lane) * 64 + f]);

    bool removed = false;
    float T = m;
#pragma unroll
    for (int r = 0; r < 4; r++) {
        float mv = removed ? 3.402823466e38f : m;
#pragma unroll
        for (int off = 16; off; off >>= 1)
            mv = fminf(mv, __shfl_xor_sync(0xffffffffu, mv, off));
        T = mv;
        unsigned ball = __ballot_sync(0xffffffffu, !removed && (m == mv));
        int leader = __ffs(ball) - 1;
        if (lane == leader) removed = true;
    }
    if (lane == 0) g_T[f] = T;
}

// ---------------- fused: blocks [0,512) MLP+collect; rest pack masks ----------------
__global__ __launch_bounds__(128) void k_main(
    const int* __restrict__ x,
    const float* __restrict__ grid,
    const float* __restrict__ w1, const float* __restrict__ b1,
    const float* __restrict__ w2, const float* __restrict__ b2,
    const float* __restrict__ w3, const float* __restrict__ b3)
{
    __shared__ float sw1[128], sb1[64], sb2[64], sb3[64], sT[64];
    __shared__ u64 sw2q[2048], sw3q[2048];
    __shared__ int sp[4];

    int tid = threadIdx.x;

    if (blockIdx.x >= NCOLBLK) {
        // ---- pack ----
        int g = (blockIdx.x - NCOLBLK) * 128 + tid;   // < NCH*NPTS
        int ch = g >> 16;
        int pos = g & 65535;
        int v = (x[g] == 1);
        unsigned ball = __ballot_sync(0xffffffffu, v);
        int lane = tid & 31, wp = tid >> 5;
        if (lane == 0) {
            g_maskT[(pos >> 5) * NCH + ch] = ball;
            sp[wp] = __popc(ball);
        }
        __syncthreads();
        if (tid == 0)
            atomicAdd(&g_popcnt[ch], sp[0] + sp[1] + sp[2] + sp[3]);
        return;
    }

    // ---- collect ----
    load_mlp_smem(w1, b1, w2, b2, w3, b3, sw1, sb1, sw2q, sb2, sw3q, sb3, tid, 128);
    if (tid < 64) sT[tid] = g_T[tid];
    __syncthreads();

    int n = blockIdx.x * 128 + tid;
    float zs[64];
    mlp_point(grid[n], grid[NPTS + n], sw1, sb1, sw2q, sb2, sw3q, sb3, zs);

#pragma unroll
    for (int k = 0; k < 64; k++) {
        if (zs[k] >= sT[k]) {
            int p = atomicAdd(&g_cnt[k], 1);
            if (p < CAP) g_cand[k * CAP + p] = make_int2(n, __float_as_int(zs[k]));
        }
    }
}

// ---------------- per-feature masked max over candidates (+ exact fallback) ----------------
__global__ __launch_bounds__(128) void k_query(
    const float* __restrict__ grid,
    const float* __restrict__ w1, const float* __restrict__ b1,
    const float* __restrict__ w2, const float* __restrict__ b2,
    const float* __restrict__ w3, const float* __restrict__ b3)
{
    __shared__ int s_nfb;
    __shared__ unsigned char sflag[NCH];
    __shared__ float sw1[128], sb1[64], sb2[64], sb3[64];
    __shared__ u64 sw2q[2048], sw3q[2048];
    __shared__ float sred[128];

    int tid = threadIdx.x;
    int f = blockIdx.x;
    int cntRaw = g_cnt[f];
    int cnt = cntRaw < CAP ? cntRaw : CAP;
    bool overflow = cntRaw > CAP;

    if (tid == 0) s_nfb = 0;
    if (tid < NCH) sflag[tid] = 0;
    __syncthreads();

    if (tid < NCH) {
        int ch = tid;
        if (g_popcnt[ch] > 0) {
            float m = -1e30f;
            bool found = false;
            if (!overflow) {
                const int2* cd = g_cand + f * CAP;
                for (int i = 0; i < cnt; i++) {
                    int2 c = __ldg(cd + i);
                    unsigned w = __ldg(&g_maskT[(c.x >> 5) * NCH + ch]);
                    if ((w >> (c.x & 31)) & 1) {
                        m = fmaxf(m, __int_as_float(c.y));
                        found = true;
                    }
                }
            }
            if (found) g_zres[ch * 64 + f] = m;
            else { sflag[ch] = 1; atomicAdd(&s_nfb, 1); }
        }
    }
    __syncthreads();
    if (s_nfb == 0) return;

    // exact dense fallback (astronomically rare): recompute MLP, masked max
    load_mlp_smem(w1, b1, w2, b2, w3, b3, sw1, sb1, sw2q, sb2, sw3q, sb3, tid, 128);
    __syncthreads();
    for (int ch = 0; ch < NCH; ch++) {
        if (!sflag[ch]) continue;
        float m = -1e30f;
        for (int base = 0; base < NPTS; base += 128) {
            int n = base + tid;
            float zs[64];
            mlp_point(grid[n], grid[NPTS + n], sw1, sb1, sw2q, sb2, sw3q, sb3, zs);
            unsigned w = g_maskT[(n >> 5) * NCH + ch];
            if ((w >> (n & 31)) & 1) m = fmaxf(m, zs[f]);
        }
        sred[tid] = m;
        __syncthreads();
        for (int off = 64; off; off >>= 1) {
            if (tid < off) sred[tid] = fmaxf(sred[tid], sred[tid + off]);
            __syncthreads();
        }
        if (tid == 0) g_zres[ch * 64 + f] = sred[0];
        __syncthreads();
    }
}

// ---------------- final FC + repeat 18 ----------------
__global__ __launch_bounds__(128) void k_fc(const float* __restrict__ fcw,
                                            const float* __restrict__ fcb,
                                            float* __restrict__ out)
{
    __shared__ float fs[NCH * NF];
    __shared__ float rw[4][4];

    int tid = threadIdx.x;
    int o = blockIdx.x;
    for (int i = tid; i < NCH * NF; i += 128) {
        int ch = i >> 6;
        fs[i] = (g_popcnt[ch] > 0) ? g_zres[i] : g_zf[i & 63];
    }
    __syncthreads();

    float p0 = 0.f, p1 = 0.f, p2 = 0.f, p3 = 0.f;
    const float* wr = fcw + o * 1216;
    for (int k = tid; k < 1216; k += 128) {
        float w = wr[k];
        p0 += w * fs[k];
        p1 += w * fs[1216 + k];
        p2 += w * fs[2432 + k];
        p3 += w * fs[3648 + k];
    }
#pragma unroll
    for (int off = 16; off; off >>= 1) {
        p0 += __shfl_xor_sync(0xffffffffu, p0, off);
        p1 += __shfl_xor_sync(0xffffffffu, p1, off);
        p2 += __shfl_xor_sync(0xffffffffu, p2, off);
        p3 += __shfl_xor_sync(0xffffffffu, p3, off);
    }
    int lane = tid & 31, wp = tid >> 5;
    if (lane == 0) { rw[wp][0] = p0; rw[wp][1] = p1; rw[wp][2] = p2; rw[wp][3] = p3; }
    __syncthreads();
    if (tid < 4) {
        float s = rw[0][tid] + rw[1][tid] + rw[2][tid] + rw[3][tid];
        float scale = rsqrtf(1216.0f);
        float val = s * scale + fcb[o];
#pragma unroll
        for (int r = 0; r < 18; r++)
            out[(tid * 18 + r) * 512 + o] = val;
    }
}

extern "C" void kernel_launch(void* const* d_in, const int* in_sizes, int n_in,
                              void* d_out, int out_size) {
    const int*   x    = (const int*)d_in[0];
    const float* grid = (const float*)d_in[1];
    const float* w1   = (const float*)d_in[2];
    const float* b1   = (const float*)d_in[3];
    const float* w2   = (const float*)d_in[4];
    const float* b2   = (const float*)d_in[5];
    const float* w3   = (const float*)d_in[6];
    const float* b3   = (const float*)d_in[7];
    const float* fcw  = (const float*)d_in[8];
    const float* fcb  = (const float*)d_in[9];
    float* out = (float*)d_out;

    k_prep<<<17, 128>>>(grid, w1, b1, w2, b2, w3, b3);
    k_select<<<NF, 32>>>();
    k_main<<<NCOLBLK + NPACKBLK, 128>>>(x, grid, w1, b1, w2, b2, w3, b3);
    k_query<<<NF, 128>>>(grid, w1, b1, w2, b2, w3, b3);
    k_fc<<<512, 128>>>(fcw, fcb, out);
}

// round 5
// speedup vs baseline: 4208.5897x; 4073.5558x over previous
#include <cuda_runtime.h>

#define NPTS 65536
#define NCH 76          // 4*19
#define NF 64
#define CAP 65536       // per-feature candidate cap == NPTS: overflow impossible
#define NSAMP 4096
#define KGUAR 32        // threshold = exact 32nd-largest sample value
#define NPACKBLK (NCH * NPTS / 128)   // 38912
#define NCOLBLK (NPTS / 128)          // 512

typedef unsigned long long u64;

__device__ unsigned g_maskT[2048 * NCH];     // [word_in_ch][ch] transposed
__device__ int      g_popcnt[NCH];
__device__ float    g_zres[NCH * NF];
__device__ float    g_zf[NF];                // zero-point fallback feature
__device__ float    g_sfeat[NSAMP * NF];     // sample features [s][f]
__device__ float    g_T[NF];                 // per-feature candidate threshold
__device__ int      g_cnt[NF];
__device__ int2     g_cand[(size_t)NF * CAP];       // (.x = point idx, .y = float bits)
__device__ float    g_feats[(size_t)NPTS * NF];     // [n][f] full features (fallback)

__device__ __forceinline__ float lrelu(float a) { return fmaxf(a, 0.01f * a); }

__device__ __forceinline__ unsigned okey(float f) {
    unsigned u = __float_as_uint(f);
    return u ^ (unsigned)(((int)u >> 31) | (int)0x80000000);
}
__device__ __forceinline__ float dekey(unsigned k) {
    unsigned u = (k & 0x80000000u) ? (k ^ 0x80000000u) : ~k;
    return __uint_as_float(u);
}

// ---- packed f32x2 helpers (sm_100+) ----
__device__ __forceinline__ u64 pk(float lo, float hi) {
    u64 r; asm("mov.b64 %0, {%1,%2};" : "=l"(r) : "f"(lo), "f"(hi)); return r;
}
__device__ __forceinline__ void unpk(u64 a, float& lo, float& hi) {
    asm("mov.b64 {%0,%1}, %2;" : "=f"(lo), "=f"(hi) : "l"(a));
}
__device__ __forceinline__ u64 ffma2(u64 a, u64 b, u64 c) {
    u64 d; asm("fma.rn.f32x2 %0, %1, %2, %3;" : "=l"(d) : "l"(a), "l"(b), "l"(c));
    return d;
}

// ---- shared-memory weight loader ----
__device__ __forceinline__ void load_mlp_smem(
    const float* w1, const float* b1, const float* w2, const float* b2,
    const float* w3, const float* b3,
    float* sw1, float* sb1, u64* sw2q, float* sb2, u64* sw3q, float* sb3,
    int tid, int nt)
{
    for (int i = tid; i < 128; i += nt) sw1[i] = w1[i];
    for (int i = tid; i < 64; i += nt) { sb1[i] = b1[i]; sb2[i] = b2[i]; sb3[i] = b3[i]; }
    for (int i = tid; i < 2048; i += nt) {
        sw2q[i] = ((const u64*)w2)[i];
        sw3q[i] = ((const u64*)w3)[i];
    }
}

// ---- full 3-layer MLP for one point (weights in smem) ----
__device__ __forceinline__ void mlp_point(
    float uu, float vv,
    const float* sw1, const float* sb1,
    const u64* sw2q, const float* sb2,
    const u64* sw3q, const float* sb3,
    float zs[64])
{
    u64 zq[32];
#pragma unroll
    for (int k = 0; k < 32; k++) {
        float a0 = fmaf(sw1[4 * k + 0], uu, fmaf(sw1[4 * k + 1], vv, sb1[2 * k]));
        float a1 = fmaf(sw1[4 * k + 2], uu, fmaf(sw1[4 * k + 3], vv, sb1[2 * k + 1]));
        zq[k] = pk(lrelu(a0), lrelu(a1));
    }
    float zt[64];
#pragma unroll
    for (int k = 0; k < 64; k++) {
        const ulonglong2* wr = (const ulonglong2*)(sw2q + k * 32);
        u64 a0 = 0ull, a1 = 0ull;
#pragma unroll
        for (int j2 = 0; j2 < 16; j2++) {
            ulonglong2 wv = wr[j2];
            a0 = ffma2(wv.x, zq[2 * j2 + 0], a0);
            a1 = ffma2(wv.y, zq[2 * j2 + 1], a1);
        }
        float l0, h0, l1, h1;
        unpk(a0, l0, h0); unpk(a1, l1, h1);
        zt[k] = lrelu((l0 + h0) + (l1 + h1) + sb2[k]);
    }
#pragma unroll
    for (int k = 0; k < 32; k++) zq[k] = pk(zt[2 * k], zt[2 * k + 1]);
#pragma unroll
    for (int k = 0; k < 64; k++) {
        const ulonglong2* wr = (const ulonglong2*)(sw3q + k * 32);
        u64 a0 = 0ull, a1 = 0ull;
#pragma unroll
        for (int j2 = 0; j2 < 16; j2++) {
            ulonglong2 wv = wr[j2];
            a0 = ffma2(wv.x, zq[2 * j2 + 0], a0);
            a1 = ffma2(wv.y, zq[2 * j2 + 1], a1);
        }
        float l0, h0, l1, h1;
        unpk(a0, l0, h0); unpk(a1, l1, h1);
        zs[k] = lrelu((l0 + h0) + (l1 + h1) + sb3[k]);
    }
}

#define SIDX(s) (((s) * 9973) & 65535)

// ---------------- prep: blocks 0..31 sample MLP; block 32 zeros + zero-feat ----------------
__global__ __launch_bounds__(128) void k_prep(
    const float* __restrict__ grid,
    const float* __restrict__ w1, const float* __restrict__ b1,
    const float* __restrict__ w2, const float* __restrict__ b2,
    const float* __restrict__ w3, const float* __restrict__ b3)
{
    int tid = threadIdx.x;
    if (blockIdx.x == NSAMP / 128) {
        __shared__ float z1[64], z2[64];
        if (tid < NCH) g_popcnt[tid] = 0;
        if (tid < NF) g_cnt[tid] = 0;
        if (tid < 64) z1[tid] = lrelu(b1[tid]);
        __syncthreads();
        if (tid < 64) {
            float a = b2[tid];
            for (int j = 0; j < 64; j++) a += w2[tid * 64 + j] * z1[j];
            z2[tid] = lrelu(a);
        }
        __syncthreads();
        if (tid < 64) {
            float a = b3[tid];
            for (int j = 0; j < 64; j++) a += w3[tid * 64 + j] * z2[j];
            g_zf[tid] = lrelu(a);
        }
        return;
    }
    __shared__ float sw1[128], sb1[64], sb2[64], sb3[64];
    __shared__ u64 sw2q[2048], sw3q[2048];
    load_mlp_smem(w1, b1, w2, b2, w3, b3, sw1, sb1, sw2q, sb2, sw3q, sb3, tid, 128);
    __syncthreads();

    int s = blockIdx.x * 128 + tid;
    int n = SIDX(s);
    float zs[64];
    mlp_point(grid[n], grid[NPTS + n], sw1, sb1, sw2q, sb2, sw3q, sb3, zs);
    float4* op = (float4*)(g_sfeat + s * 64);
#pragma unroll
    for (int k = 0; k < 16; k++)
        op[k] = make_float4(zs[4 * k], zs[4 * k + 1], zs[4 * k + 2], zs[4 * k + 3]);
}

// ---------------- select: exact KGUAR-th largest of NSAMP samples per feature ----------------
__global__ __launch_bounds__(32) void k_select() {
    int f = blockIdx.x;
    int lane = threadIdx.x;
    unsigned keys[NSAMP / 32];
#pragma unroll
    for (int i = 0; i < NSAMP / 32; i++)
        keys[i] = okey(g_sfeat[(i * 32 + lane) * 64 + f]);

    // greedy MSB->LSB: largest T with count(keys >= T) >= KGUAR
    unsigned T = 0u;
#pragma unroll
    for (int bit = 31; bit >= 0; bit--) {
        unsigned cand = T | (1u << bit);
        int c = 0;
#pragma unroll
        for (int i = 0; i < NSAMP / 32; i++) c += (keys[i] >= cand);
        c += __shfl_xor_sync(0xffffffffu, c, 16);
        c += __shfl_xor_sync(0xffffffffu, c, 8);
        c += __shfl_xor_sync(0xffffffffu, c, 4);
        c += __shfl_xor_sync(0xffffffffu, c, 2);
        c += __shfl_xor_sync(0xffffffffu, c, 1);
        if (c >= KGUAR) T = cand;
    }
    if (lane == 0) g_T[f] = dekey(T);
}

// ---------------- fused: blocks [0,512) MLP+collect+store; rest pack masks ----------------
__global__ __launch_bounds__(128) void k_main(
    const int* __restrict__ x,
    const float* __restrict__ grid,
    const float* __restrict__ w1, const float* __restrict__ b1,
    const float* __restrict__ w2, const float* __restrict__ b2,
    const float* __restrict__ w3, const float* __restrict__ b3)
{
    __shared__ float sw1[128], sb1[64], sb2[64], sb3[64], sT[64];
    __shared__ u64 sw2q[2048], sw3q[2048];
    __shared__ int sp[4];

    int tid = threadIdx.x;

    if (blockIdx.x >= NCOLBLK) {
        // ---- pack masks ----
        int g = (blockIdx.x - NCOLBLK) * 128 + tid;   // < NCH*NPTS
        int ch = g >> 16;
        int pos = g & 65535;
        int v = (x[g] == 1);
        unsigned ball = __ballot_sync(0xffffffffu, v);
        int lane = tid & 31, wp = tid >> 5;
        if (lane == 0) {
            g_maskT[(pos >> 5) * NCH + ch] = ball;
            sp[wp] = __popc(ball);
        }
        __syncthreads();
        if (tid == 0)
            atomicAdd(&g_popcnt[ch], sp[0] + sp[1] + sp[2] + sp[3]);
        return;
    }

    // ---- collect ----
    load_mlp_smem(w1, b1, w2, b2, w3, b3, sw1, sb1, sw2q, sb2, sw3q, sb3, tid, 128);
    if (tid < 64) sT[tid] = g_T[tid];
    __syncthreads();

    int n = blockIdx.x * 128 + tid;
    float zs[64];
    mlp_point(grid[n], grid[NPTS + n], sw1, sb1, sw2q, sb2, sw3q, sb3, zs);

    float4* op = (float4*)(g_feats + (size_t)n * 64);
#pragma unroll
    for (int k = 0; k < 16; k++)
        op[k] = make_float4(zs[4 * k], zs[4 * k + 1], zs[4 * k + 2], zs[4 * k + 3]);

#pragma unroll
    for (int k = 0; k < 64; k++) {
        if (zs[k] >= sT[k]) {
            int p = atomicAdd(&g_cnt[k], 1);
            g_cand[(size_t)k * CAP + p] = make_int2(n, __float_as_int(zs[k]));
        }
    }
}

// ---------------- per-feature masked max over candidates (+ cheap exact fallback) ----------------
__global__ __launch_bounds__(128) void k_query() {
    __shared__ int s_nfb;
    __shared__ unsigned char sflag[NCH];
    __shared__ float sred[128];

    int tid = threadIdx.x;
    int f = blockIdx.x;
    int cnt = g_cnt[f];           // <= CAP by construction

    if (tid == 0) s_nfb = 0;
    if (tid < NCH) sflag[tid] = 0;
    __syncthreads();

    if (tid < NCH) {
        int ch = tid;
        if (g_popcnt[ch] > 0) {
            float m = -1e30f;
            bool found = false;
            const int2* cd = g_cand + (size_t)f * CAP;
            for (int i = 0; i < cnt; i++) {
                int2 c = __ldg(cd + i);
                unsigned w = __ldg(&g_maskT[(c.x >> 5) * NCH + ch]);
                if ((w >> (c.x & 31)) & 1) {
                    m = fmaxf(m, __int_as_float(c.y));
                    found = true;
                }
            }
            if (found) g_zres[ch * 64 + f] = m;
            else { sflag[ch] = 1; atomicAdd(&s_nfb, 1); }
        }
    }
    __syncthreads();
    if (s_nfb == 0) return;

    // exact fallback (P ~ 2^-32 per pair): dense scan of stored feature column
    for (int ch = 0; ch < NCH; ch++) {
        if (!sflag[ch]) continue;
        float m = -1e30f;
        for (int base = 0; base < NPTS; base += 128) {
            int n = base + tid;
            float v = __ldg(&g_feats[(size_t)n * 64 + f]);
            unsigned w = g_maskT[(n >> 5) * NCH + ch];
            if ((w >> (n & 31)) & 1) m = fmaxf(m, v);
        }
        sred[tid] = m;
        __syncthreads();
        for (int off = 64; off; off >>= 1) {
            if (tid < off) sred[tid] = fmaxf(sred[tid], sred[tid + off]);
            __syncthreads();
        }
        if (tid == 0) g_zres[ch * 64 + f] = sred[0];
        __syncthreads();
    }
}

// ---------------- final FC + repeat 18 ----------------
__global__ __launch_bounds__(128) void k_fc(const float* __restrict__ fcw,
                                            const float* __restrict__ fcb,
                                            float* __restrict__ out)
{
    __shared__ float fs[NCH * NF];
    __shared__ float rw[4][4];

    int tid = threadIdx.x;
    int o = blockIdx.x;
    for (int i = tid; i < NCH * NF; i += 128) {
        int ch = i >> 6;
        fs[i] = (g_popcnt[ch] > 0) ? g_zres[i] : g_zf[i & 63];
    }
    __syncthreads();

    float p0 = 0.f, p1 = 0.f, p2 = 0.f, p3 = 0.f;
    const float* wr = fcw + o * 1216;
    for (int k = tid; k < 1216; k += 128) {
        float w = wr[k];
        p0 += w * fs[k];
        p1 += w * fs[1216 + k];
        p2 += w * fs[2432 + k];
        p3 += w * fs[3648 + k];
    }
#pragma unroll
    for (int off = 16; off; off >>= 1) {
        p0 += __shfl_xor_sync(0xffffffffu, p0, off);
        p1 += __shfl_xor_sync(0xffffffffu, p1, off);
        p2 += __shfl_xor_sync(0xffffffffu, p2, off);
        p3 += __shfl_xor_sync(0xffffffffu, p3, off);
    }
    int lane = tid & 31, wp = tid >> 5;
    if (lane == 0) { rw[wp][0] = p0; rw[wp][1] = p1; rw[wp][2] = p2; rw[wp][3] = p3; }
    __syncthreads();
    if (tid < 4) {
        float s = rw[0][tid] + rw[1][tid] + rw[2][tid] + rw[3][tid];
        float scale = rsqrtf(1216.0f);
        float val = s * scale + fcb[o];
#pragma unroll
        for (int r = 0; r < 18; r++)
            out[(tid * 18 + r) * 512 + o] = val;
    }
}

extern "C" void kernel_launch(void* const* d_in, const int* in_sizes, int n_in,
                              void* d_out, int out_size) {
    const int*   x    = (const int*)d_in[0];
    const float* grid = (const float*)d_in[1];
    const float* w1   = (const float*)d_in[2];
    const float* b1   = (const float*)d_in[3];
    const float* w2   = (const float*)d_in[4];
    const float* b2   = (const float*)d_in[5];
    const float* w3   = (const float*)d_in[6];
    const float* b3   = (const float*)d_in[7];
    const float* fcw  = (const float*)d_in[8];
    const float* fcb  = (const float*)d_in[9];
    float* out = (float*)d_out;

    k_prep<<<NSAMP / 128 + 1, 128>>>(grid, w1, b1, w2, b2, w3, b3);
    k_select<<<NF, 32>>>();
    k_main<<<NCOLBLK + NPACKBLK, 128>>>(x, grid, w1, b1, w2, b2, w3, b3);
    k_query<<<NF, 128>>>();
    k_fc<<<512, 128>>>(fcw, fcb, out);
}